// round 17
// baseline (speedup 1.0000x reference)
#include <cuda_runtime.h>

// Problem constants
#define NCH   8192
#define NTT   4096
#define NLAGS 103
#define RAWS  112
#define XCOR_N (NCH * NLAGS)

// Stage-1 tile: 4 warps; exact lag split {26,26,26,25}, bases {0,26,52,78}.
// d1 stored UNshifted at float offset 64 => d1pad[x] = a_sm[x + 13].
#define T1     128
#define A_OFF  64            // where d1[0] lands in a_sm (16B aligned)
#define A_SZ   4224          // covers max read index 4211
#define SMEM1  ((A_SZ + NTT) * 4)   // 33.25 KB dynamic (stage2 aliases it)
#define CPB    8             // stage2 channels per group (measured optimum)

// Raw xcorr scratch: 8192 x 112 f32 (~3.67 MB, L2-resident)
__device__ float g_raw[(size_t)NCH * RAWS];
// Monotonic barrier counter (never reset; target derived per replay epoch)
__device__ unsigned g_done;

// ---------------------------------------------------------------------------
// Per-warp correlation: L lags, window offset OFF from the aligned base a_al.
// Lane handles 4 consecutive t per iter; 32 iters cover 4096 t.
// ---------------------------------------------------------------------------
template<int L, int OFF>
__device__ __forceinline__ void corr_warp(const float* __restrict__ a_al,
                                          const float* __restrict__ b_sm,
                                          int lane,
                                          float* __restrict__ outRow)
{
    constexpr int NV = (OFF + L + 3 + 3) / 4;   // float4 loads covering window

    float acc[L];
#pragma unroll
    for (int j = 0; j < L; ++j) acc[j] = 0.0f;

#pragma unroll 1
    for (int it = 0; it < 32; ++it) {
        const int t0 = it * 128 + lane * 4;

        float aw[NV * 4];
#pragma unroll
        for (int v = 0; v < NV; ++v) {
            const float4 w = *reinterpret_cast<const float4*>(a_al + t0 + 4 * v);
            aw[4 * v + 0] = w.x; aw[4 * v + 1] = w.y;
            aw[4 * v + 2] = w.z; aw[4 * v + 3] = w.w;
        }
        const float4 b4 = *reinterpret_cast<const float4*>(b_sm + t0);
        float bv[4];
        bv[0] = b4.x; bv[1] = b4.y; bv[2] = b4.z; bv[3] = b4.w;

#pragma unroll
        for (int k = 0; k < 4; ++k) {
#pragma unroll
            for (int j = 0; j < L; ++j) {
                acc[j] = fmaf(aw[OFF + j + k], bv[k], acc[j]);
            }
        }
    }

#pragma unroll
    for (int j = 0; j < L; ++j) {
#pragma unroll
        for (int o = 16; o > 0; o >>= 1)
            acc[j] += __shfl_xor_sync(0xffffffffu, acc[j], o);
    }
    if (lane == 0) {
#pragma unroll
        for (int j = 0; j < L; ++j) outRow[j] = acc[j];
    }
}

// ---------------------------------------------------------------------------
// Fused persistent kernel.
// Phase 1: channels c = bid, bid+nb, ... : R[c][l] = sum_t d1pad[t+l]*d2[t].
// Global barrier (all nb blocks co-resident by construction).
// Phase 2: groups g = bid, bid+nb, ... : channel moving average (window
// [c-10, c+9], zero-padded) + argmax|R| / max / min / tmax.
// ---------------------------------------------------------------------------
__global__ __launch_bounds__(T1, 6)
void xcorr_fused(const float* __restrict__ d1, const float* __restrict__ d2,
                 float* __restrict__ out, int nb)
{
    extern __shared__ __align__(16) float sm[];
    float* a_sm = sm;            // [A_SZ]; d1 at [A_OFF, A_OFF+NTT)
    float* b_sm = sm + A_SZ;     // [NTT]

    const int tid  = threadIdx.x;
    const int warp = tid >> 5;
    const int lane = tid & 31;

    // ---------------- Phase 1: correlation ----------------
    for (int c = blockIdx.x; c < NCH; c += nb) {
        __syncthreads();   // previous iteration's readers done before refill

        const float* __restrict__ r1 = d1 + (size_t)c * NTT;
        const float* __restrict__ r2 = d2 + (size_t)c * NTT;

        for (int i = tid; i < A_OFF / 4; i += T1)
            reinterpret_cast<float4*>(a_sm)[i] = make_float4(0.f, 0.f, 0.f, 0.f);
        for (int i = tid; i < (A_SZ - A_OFF - NTT) / 4; i += T1)
            reinterpret_cast<float4*>(a_sm + A_OFF + NTT)[i] = make_float4(0.f, 0.f, 0.f, 0.f);
        for (int k = tid; k < NTT / 4; k += T1) {
            reinterpret_cast<float4*>(a_sm + A_OFF)[k] = reinterpret_cast<const float4*>(r1)[k];
            reinterpret_cast<float4*>(b_sm)[k]         = reinterpret_cast<const float4*>(r2)[k];
        }
        __syncthreads();

        const int slot = (warp + c) & 3;   // rotate for SMSP balance
        float* row = g_raw + (size_t)c * RAWS;
        switch (slot) {
            case 0: corr_warp<26, 1>(a_sm + 12, b_sm, lane, row + 0);  break;
            case 1: corr_warp<26, 3>(a_sm + 36, b_sm, lane, row + 26); break;
            case 2: corr_warp<26, 1>(a_sm + 64, b_sm, lane, row + 52); break;
            default: corr_warp<25, 3>(a_sm + 88, b_sm, lane, row + 78); break;
        }
    }

    // ---------------- Global barrier (monotonic, reset-free) ----------------
    __syncthreads();
    if (tid == 0) {
        __threadfence();                              // release g_raw writes
        const unsigned old    = atomicAdd(&g_done, 1u);
        const unsigned target = (old / (unsigned)nb) * (unsigned)nb + (unsigned)nb;
        while (atomicAdd(&g_done, 0u) < target) __nanosleep(64);
        __threadfence();                              // acquire others' writes
    }
    __syncthreads();

    // ---------------- Phase 2: moving average + pick ----------------
    float* sh = sm;   // alias dynamic smem: [CPB][NLAGS+1]

    for (int g = blockIdx.x; g < NCH / CPB; g += nb) {
        __syncthreads();   // previous group's readers done before overwrite
        const int c0 = g * CPB;

        if (tid < NLAGS) {
            float x[CPB + 19];
#pragma unroll
            for (int i = 0; i < CPB + 19; ++i) {
                const int ch = c0 - 10 + i;
                x[i] = (ch >= 0 && ch < NCH) ? g_raw[(size_t)ch * RAWS + tid] : 0.0f;
            }
            float s = 0.0f;
#pragma unroll
            for (int i = 0; i < 20; ++i) s += x[i];
#pragma unroll
            for (int cc = 0; cc < CPB; ++cc) {
                const float m = s * (1.0f / 20.0f);
                sh[cc * (NLAGS + 1) + tid] = m;
                out[(size_t)(c0 + cc) * NLAGS + tid] = m;
                if (cc + 1 < CPB) s += x[cc + 20] - x[cc];
            }
        }
        __syncthreads();

        for (int cc = warp; cc < CPB; cc += 4) {
            float bestAbs = -1.0f;
            int   bestIdx = 0;
            float bestVal = 0.0f;
            float vpos = -3.402823466e38f;
            float vneg =  3.402823466e38f;

            for (int l = lane; l < NLAGS; l += 32) {
                const float v  = sh[cc * (NLAGS + 1) + l];
                const float av = fabsf(v);
                if (av > bestAbs) { bestAbs = av; bestIdx = l; bestVal = v; }
                vpos = fmaxf(vpos, v);
                vneg = fminf(vneg, v);
            }
#pragma unroll
            for (int o = 16; o > 0; o >>= 1) {
                const float oa = __shfl_down_sync(0xffffffffu, bestAbs, o);
                const int   oi = __shfl_down_sync(0xffffffffu, bestIdx, o);
                const float ov = __shfl_down_sync(0xffffffffu, bestVal, o);
                if (oa > bestAbs || (oa == bestAbs && oi < bestIdx)) {
                    bestAbs = oa; bestIdx = oi; bestVal = ov;
                }
                vpos = fmaxf(vpos, __shfl_down_sync(0xffffffffu, vpos, o));
                vneg = fminf(vneg, __shfl_down_sync(0xffffffffu, vneg, o));
            }

            if (lane == 0) {
                const int   ch    = c0 + cc;
                const float vside = (bestVal >= 0.0f) ? vneg : vpos;
                out[(size_t)XCOR_N + ch]           = bestVal;
                out[(size_t)XCOR_N + NCH + ch]     = vside;
                out[(size_t)XCOR_N + 2 * NCH + ch] = (float)(bestIdx - 51) * 0.01f;
            }
        }
    }
}

// ---------------------------------------------------------------------------
// kernel_launch: inputs: data1 (f32, NC*NT), data2 (f32, NC*NT), event1,
// event2 (i32, unused by the reference).
// Grid = SMs x achievable-occupancy so ALL blocks are co-resident (the spin
// barrier is deadlock-free by construction). Queries are host-side, no
// allocation, capture-safe, deterministic.
// ---------------------------------------------------------------------------
extern "C" void kernel_launch(void* const* d_in, const int* in_sizes, int n_in,
                              void* d_out, int out_size)
{
    const float* data1 = (const float*)d_in[0];
    const float* data2 = (const float*)d_in[1];
    float* out = (float*)d_out;

    int dev = 0;
    cudaGetDevice(&dev);
    int nsm = 148;
    cudaDeviceGetAttribute(&nsm, cudaDevAttrMultiProcessorCount, dev);
    int maxb = 0;
    cudaOccupancyMaxActiveBlocksPerMultiprocessor(&maxb, xcorr_fused, T1, SMEM1);
    if (maxb < 1) maxb = 1;

    int grid = nsm * maxb;
    if (grid > NCH) grid = NCH;

    xcorr_fused<<<grid, T1, SMEM1>>>(data1, data2, out, grid);
}